// round 16
// baseline (speedup 1.0000x reference)
#include <cuda_runtime.h>
#include <cuda_fp16.h>
#include <cstdint>

#define S_LEN 2048
#define DM    1024
#define NH    16
#define DKH   64
#define BB    2

// scratch: [B,H,S,DK] layouts
__device__ float g_q[BB*NH*S_LEN*DKH];
__device__ float g_k[BB*NH*S_LEN*DKH];
__device__ float g_v[BB*NH*S_LEN*DKH];
__device__ float g_attn[BB*NH*S_LEN*DKH];

// ---------------------------------------------------------------------------
// MMA helpers (warp-level, fp16 in / f32 out)
// ---------------------------------------------------------------------------
__device__ __forceinline__ void ldsm_x4(uint32_t& r0, uint32_t& r1, uint32_t& r2, uint32_t& r3,
                                        uint32_t addr) {
    asm volatile("ldmatrix.sync.aligned.m8n8.x4.shared.b16 {%0,%1,%2,%3}, [%4];"
                 : "=r"(r0), "=r"(r1), "=r"(r2), "=r"(r3) : "r"(addr));
}

__device__ __forceinline__ void ldsm_x4_t(uint32_t& r0, uint32_t& r1, uint32_t& r2, uint32_t& r3,
                                          uint32_t addr) {
    asm volatile("ldmatrix.sync.aligned.m8n8.x4.trans.shared.b16 {%0,%1,%2,%3}, [%4];"
                 : "=r"(r0), "=r"(r1), "=r"(r2), "=r"(r3) : "r"(addr));
}

__device__ __forceinline__ void mma_f16(float* c, const uint32_t* a, const uint32_t* b) {
    asm volatile(
        "mma.sync.aligned.m16n8k16.row.col.f32.f16.f16.f32 "
        "{%0,%1,%2,%3}, {%4,%5,%6,%7}, {%8,%9}, {%0,%1,%2,%3};"
        : "+f"(c[0]), "+f"(c[1]), "+f"(c[2]), "+f"(c[3])
        : "r"(a[0]), "r"(a[1]), "r"(a[2]), "r"(a[3]), "r"(b[0]), "r"(b[1]));
}

// split 8 floats into fp16 hi/lo and store 16B each
__device__ __forceinline__ void split_store_h(float4 u0, float4 u1,
                                              __half* dst_hi, __half* dst_lo) {
    float x[8] = {u0.x, u0.y, u0.z, u0.w, u1.x, u1.y, u1.z, u1.w};
    __half2 h[4], l[4];
    #pragma unroll
    for (int i = 0; i < 4; i++) {
        float a = x[2*i], b = x[2*i+1];
        __half ha = __float2half_rn(a);
        __half hb = __float2half_rn(b);
        __half la = __float2half_rn(a - __half2float(ha));
        __half lb = __float2half_rn(b - __half2float(hb));
        h[i] = __halves2half2(ha, hb);
        l[i] = __halves2half2(la, lb);
    }
    *(uint4*)dst_hi = *(uint4*)h;
    *(uint4*)dst_lo = *(uint4*)l;
}

// convert 8 floats to single fp16, store 16B
__device__ __forceinline__ void cvt_store_h(float4 u0, float4 u1, __half* dst) {
    __half2 h[4];
    h[0] = __floats2half2_rn(u0.x, u0.y);
    h[1] = __floats2half2_rn(u0.z, u0.w);
    h[2] = __floats2half2_rn(u1.x, u1.y);
    h[3] = __floats2half2_rn(u1.z, u1.w);
    *(uint4*)dst = *(uint4*)h;
}

__device__ __forceinline__ uint32_t pack_h(float a, float b) {
    __half2 t = __floats2half2_rn(a, b);
    return *(uint32_t*)&t;
}

// smem layout constants for the GEMM kernels (2-term: A single, B hi/lo)
#define LDAB 24                 // fp16 per row (16 data + 8 pad)
#define T_A    0
#define T_B_HI (128*LDAB)
#define T_B_LO (2*128*LDAB)
#define G_STAGE_EL (3*128*LDAB)     // elements per stage = 9216
#define G_STAGE_B  (G_STAGE_EL*2)   // bytes per stage = 18432

// ---------------------------------------------------------------------------
// QKV projection: double-buffered 2-term fp16 GEMM (A single, B split hi/lo).
// ---------------------------------------------------------------------------
__global__ __launch_bounds__(256, 2) void qkv_proj_kernel(
    const float* __restrict__ xq, const float* __restrict__ xk, const float* __restrict__ xv,
    const float* __restrict__ Wq, const float* __restrict__ bq,
    const float* __restrict__ Wk, const float* __restrict__ bk,
    const float* __restrict__ Wv, const float* __restrict__ bv)
{
    int z = blockIdx.z;
    const float* X    = (z == 0) ? xq : (z == 1) ? xk : xv;
    const float* W    = (z == 0) ? Wq : (z == 1) ? Wk : Wv;
    const float* bias = (z == 0) ? bq : (z == 1) ? bk : bv;
    float* out        = (z == 0) ? g_q : (z == 1) ? g_k : g_v;

    __shared__ __align__(16) __half sm[2*G_STAGE_EL];   // 36 KB

    int tid  = threadIdx.x;
    int lane = tid & 31;
    int wid  = tid >> 5;
    int wm   = wid & 1;
    int wn   = wid >> 1;
    int m0 = blockIdx.y * 128;
    int n0 = blockIdx.x * 128;

    int grow = tid >> 1;
    int gk8  = (tid & 1) * 8;
    const float* Abase = X + (size_t)(m0 + grow) * DM + gk8;
    const float* Bbase = W + (size_t)(n0 + grow) * DM + gk8;
    __half* sa    = sm + T_A    + grow * LDAB + gk8;
    __half* sb_hi = sm + T_B_HI + grow * LDAB + gk8;
    __half* sb_lo = sm + T_B_LO + grow * LDAB + gk8;

    uint32_t smem_u32 = (uint32_t)__cvta_generic_to_shared(sm);
    int a_row = lane & 15, a_kh = (lane >> 4) * 8;
    uint32_t adA[4];
    #pragma unroll
    for (int mt = 0; mt < 4; mt++) {
        int r = wm * 64 + mt * 16 + a_row;
        adA[mt] = smem_u32 + (uint32_t)(T_A + r * LDAB + a_kh) * 2;
    }
    int b_nrow = ((lane >> 4) & 1) * 8 + (lane & 7);
    int b_k    = ((lane >> 3) & 1) * 8;
    uint32_t adB[2], adBlo[2];
    #pragma unroll
    for (int p = 0; p < 2; p++) {
        int r = wn * 32 + p * 16 + b_nrow;
        adB[p]   = smem_u32 + (uint32_t)(T_B_HI + r * LDAB + b_k) * 2;
        adBlo[p] = smem_u32 + (uint32_t)(T_B_LO + r * LDAB + b_k) * 2;
    }

    float C[4][4][4] = {};

    float4 a0 = *(const float4*)(Abase + 0);
    float4 a1 = *(const float4*)(Abase + 4);
    float4 b0 = *(const float4*)(Bbase + 0);
    float4 b1 = *(const float4*)(Bbase + 4);

    cvt_store_h(a0, a1, sa);
    split_store_h(b0, b1, sb_hi, sb_lo);
    __syncthreads();

    uint32_t curB = 0;
    int      curE = 0;

    for (int k0 = 0; k0 < DM; k0 += 16) {
        bool more = (k0 + 16) < DM;
        if (more) {
            a0 = *(const float4*)(Abase + k0 + 16);
            a1 = *(const float4*)(Abase + k0 + 20);
            b0 = *(const float4*)(Bbase + k0 + 16);
            b1 = *(const float4*)(Bbase + k0 + 20);
        }

        uint32_t A[4][4], Bh[4][2], Bl[4][2];
        #pragma unroll
        for (int mt = 0; mt < 4; mt++)
            ldsm_x4(A[mt][0], A[mt][1], A[mt][2], A[mt][3], adA[mt] + curB);
        #pragma unroll
        for (int p = 0; p < 2; p++) {
            uint32_t r0, r1, r2, r3;
            ldsm_x4(r0, r1, r2, r3, adB[p] + curB);
            Bh[p*2+0][0] = r0; Bh[p*2+0][1] = r1;
            Bh[p*2+1][0] = r2; Bh[p*2+1][1] = r3;
            ldsm_x4(r0, r1, r2, r3, adBlo[p] + curB);
            Bl[p*2+0][0] = r0; Bl[p*2+0][1] = r1;
            Bl[p*2+1][0] = r2; Bl[p*2+1][1] = r3;
        }
        #pragma unroll
        for (int mt = 0; mt < 4; mt++)
            #pragma unroll
            for (int nt = 0; nt < 4; nt++) {
                mma_f16(C[mt][nt], A[mt], Bh[nt]);
                mma_f16(C[mt][nt], A[mt], Bl[nt]);
            }

        if (more) {
            int nx = curE ^ G_STAGE_EL;
            cvt_store_h(a0, a1, sa + nx);
            split_store_h(b0, b1, sb_hi + nx, sb_lo + nx);
        }
        __syncthreads();
        curB ^= G_STAGE_B;
        curE ^= G_STAGE_EL;
    }

    int crow = lane >> 2;
    int ccol = (lane & 3) * 2;
    #pragma unroll
    for (int nt = 0; nt < 4; nt++) {
        int n = n0 + wn * 32 + nt * 8 + ccol;
        int h = n >> 6, dk = n & 63;
        float bi0 = bias[n], bi1 = bias[n + 1];
        #pragma unroll
        for (int mt = 0; mt < 4; mt++) {
            #pragma unroll
            for (int half = 0; half < 2; half++) {
                int m = m0 + wm * 64 + mt * 16 + crow + half * 8;
                int b_ = m >> 11, s = m & 2047;
                float* op = out + (((size_t)(b_ * NH + h)) * S_LEN + s) * DKH + dk;
                float2 r = make_float2(C[mt][nt][half*2+0] + bi0, C[mt][nt][half*2+1] + bi1);
                *(float2*)op = r;
            }
        }
    }
}

// ---------------------------------------------------------------------------
// Output projection: same 2-term structure, head-gathered A.
// ---------------------------------------------------------------------------
__global__ __launch_bounds__(256, 2) void out_proj_kernel(
    const float* __restrict__ Wo, const float* __restrict__ bo, float* __restrict__ out)
{
    __shared__ __align__(16) __half sm[2*G_STAGE_EL];

    int tid  = threadIdx.x;
    int lane = tid & 31;
    int wid  = tid >> 5;
    int wm   = wid & 1;
    int wn   = wid >> 1;
    int m0 = blockIdx.y * 128;
    int n0 = blockIdx.x * 128;

    int grow = tid >> 1;
    int gk8  = (tid & 1) * 8;
    int m  = m0 + grow;
    int b_ = m >> 11, ss = m & 2047;
    const float* arow = g_attn + ((size_t)b_ * NH) * S_LEN * DKH + (size_t)ss * DKH;
    const float* Bbase = Wo + (size_t)(n0 + grow) * DM + gk8;
    __half* sa    = sm + T_A    + grow * LDAB + gk8;
    __half* sb_hi = sm + T_B_HI + grow * LDAB + gk8;
    __half* sb_lo = sm + T_B_LO + grow * LDAB + gk8;

    auto lda = [&](int k) -> float4 {
        return *(const float4*)(arow + (size_t)(k >> 6) * (S_LEN * DKH) + (k & 63));
    };

    uint32_t smem_u32 = (uint32_t)__cvta_generic_to_shared(sm);
    int a_row = lane & 15, a_kh = (lane >> 4) * 8;
    uint32_t adA[4];
    #pragma unroll
    for (int mt = 0; mt < 4; mt++) {
        int r = wm * 64 + mt * 16 + a_row;
        adA[mt] = smem_u32 + (uint32_t)(T_A + r * LDAB + a_kh) * 2;
    }
    int b_nrow = ((lane >> 4) & 1) * 8 + (lane & 7);
    int b_k    = ((lane >> 3) & 1) * 8;
    uint32_t adB[2], adBlo[2];
    #pragma unroll
    for (int p = 0; p < 2; p++) {
        int r = wn * 32 + p * 16 + b_nrow;
        adB[p]   = smem_u32 + (uint32_t)(T_B_HI + r * LDAB + b_k) * 2;
        adBlo[p] = smem_u32 + (uint32_t)(T_B_LO + r * LDAB + b_k) * 2;
    }

    float C[4][4][4] = {};

    float4 a0 = lda(gk8);
    float4 a1 = lda(gk8 + 4);
    float4 b0 = *(const float4*)(Bbase + 0);
    float4 b1 = *(const float4*)(Bbase + 4);

    cvt_store_h(a0, a1, sa);
    split_store_h(b0, b1, sb_hi, sb_lo);
    __syncthreads();

    uint32_t curB = 0;
    int      curE = 0;

    for (int k0 = 0; k0 < DM; k0 += 16) {
        bool more = (k0 + 16) < DM;
        if (more) {
            a0 = lda(k0 + 16 + gk8);
            a1 = lda(k0 + 16 + gk8 + 4);
            b0 = *(const float4*)(Bbase + k0 + 16);
            b1 = *(const float4*)(Bbase + k0 + 20);
        }

        uint32_t A[4][4], Bh[4][2], Bl[4][2];
        #pragma unroll
        for (int mt = 0; mt < 4; mt++)
            ldsm_x4(A[mt][0], A[mt][1], A[mt][2], A[mt][3], adA[mt] + curB);
        #pragma unroll
        for (int p = 0; p < 2; p++) {
            uint32_t r0, r1, r2, r3;
            ldsm_x4(r0, r1, r2, r3, adB[p] + curB);
            Bh[p*2+0][0] = r0; Bh[p*2+0][1] = r1;
            Bh[p*2+1][0] = r2; Bh[p*2+1][1] = r3;
            ldsm_x4(r0, r1, r2, r3, adBlo[p] + curB);
            Bl[p*2+0][0] = r0; Bl[p*2+0][1] = r1;
            Bl[p*2+1][0] = r2; Bl[p*2+1][1] = r3;
        }
        #pragma unroll
        for (int mt = 0; mt < 4; mt++)
            #pragma unroll
            for (int nt = 0; nt < 4; nt++) {
                mma_f16(C[mt][nt], A[mt], Bh[nt]);
                mma_f16(C[mt][nt], A[mt], Bl[nt]);
            }

        if (more) {
            int nx = curE ^ G_STAGE_EL;
            cvt_store_h(a0, a1, sa + nx);
            split_store_h(b0, b1, sb_hi + nx, sb_lo + nx);
        }
        __syncthreads();
        curB ^= G_STAGE_B;
        curE ^= G_STAGE_EL;
    }

    int crow = lane >> 2;
    int ccol = (lane & 3) * 2;
    #pragma unroll
    for (int nt = 0; nt < 4; nt++) {
        int n = n0 + wn * 32 + nt * 8 + ccol;
        float bi0 = bo[n], bi1 = bo[n + 1];
        #pragma unroll
        for (int mt = 0; mt < 4; mt++) {
            #pragma unroll
            for (int half = 0; half < 2; half++) {
                int mr = m0 + wm * 64 + mt * 16 + crow + half * 8;
                float2 r = make_float2(C[mt][nt][half*2+0] + bi0, C[mt][nt][half*2+1] + bi1);
                *(float2*)(out + (size_t)mr * DM + n) = r;
            }
        }
    }
}

// ---------------------------------------------------------------------------
// Flash attention (unchanged from R9): QK = Qh*Kh [1 MMA], PV = P*(Vh+Vl) [2 MMA].
// CTA: 128 q rows x one (b,h); 8 warps x 16 q rows; kv tiles of 64, 2-stage.
// Stage layout (rows of LDK): K single [0-63], V hi [64-127], V lo [128-191].
// ---------------------------------------------------------------------------
#define LDK 72
#define A_STAGE_EL (192*LDK)        // elements per stage = 13824
#define A_STAGE_B  (A_STAGE_EL*2)   // 27648 bytes

extern __shared__ __half dsm[];

__global__ __launch_bounds__(256) void attn_kernel(const int* __restrict__ mask)
{
    const float MSCALE = 0.125f * 1.44269504f;   // (1/8) * log2(e)
    const float MNEG   = -1.442695e9f;           // -1e9 * log2(e)

    int tid  = threadIdx.x;
    int lane = tid & 31;
    int warp = tid >> 5;
    int bh = blockIdx.y;
    int b  = bh >> 4;
    int q0 = blockIdx.x * 128;

    const float* Qg = g_q + (size_t)bh * S_LEN * DKH;
    const float* Kg = g_k + (size_t)bh * S_LEN * DKH;
    const float* Vg = g_v + (size_t)bh * S_LEN * DKH;

    uint32_t base = (uint32_t)__cvta_generic_to_shared(dsm);

    // ---- stage Q (single fp16) into stage0 rows 0-127 ----
    {
        int row = tid >> 1;
        int c0 = (tid & 1) * 32;
        const float* src = Qg + (size_t)(q0 + row) * DKH + c0;
        #pragma unroll
        for (int c = 0; c < 32; c += 8) {
            float4 u0 = *(const float4*)(src + c);
            float4 u1 = *(const float4*)(src + c + 4);
            cvt_store_h(u0, u1, dsm + row*LDK + c0 + c);
        }
    }
    __syncthreads();

    // ---- Q A-fragments (resident all kernel) ----
    uint32_t Qh[4][4];
    {
        int a_row = lane & 15, a_kh = (lane >> 4) * 8;
        #pragma unroll
        for (int kt = 0; kt < 4; kt++) {
            uint32_t off = (uint32_t)((warp*16 + a_row)*LDK + kt*16 + a_kh) * 2;
            ldsm_x4(Qh[kt][0], Qh[kt][1], Qh[kt][2], Qh[kt][3], base + off);
        }
    }
    __syncthreads();   // done reading Q staging before overwriting stage0

    // ---- stage kv tile 0 into stage0 ----
    int row4 = tid >> 2;           // 0..63
    int c04  = (tid & 3) * 16;     // 0,16,32,48
    {
        const float* ks = Kg + (size_t)row4 * DKH + c04;
        const float* vs = Vg + (size_t)row4 * DKH + c04;
        float4 k0_ = *(const float4*)(ks + 0), k1_ = *(const float4*)(ks + 4);
        float4 k2_ = *(const float4*)(ks + 8), k3_ = *(const float4*)(ks + 12);
        cvt_store_h(k0_, k1_, dsm + row4*LDK + c04);
        cvt_store_h(k2_, k3_, dsm + row4*LDK + c04 + 8);
        float4 w0 = *(const float4*)(vs + 0), w1 = *(const float4*)(vs + 4);
        float4 w2 = *(const float4*)(vs + 8), w3 = *(const float4*)(vs + 12);
        split_store_h(w0, w1, dsm + (64+row4)*LDK + c04,     dsm + (128+row4)*LDK + c04);
        split_store_h(w2, w3, dsm + (64+row4)*LDK + c04 + 8, dsm + (128+row4)*LDK + c04 + 8);
    }
    __syncthreads();

    float m_i[2] = {-1e30f, -1e30f};
    float l_i[2] = {0.f, 0.f};
    float O[8][4] = {};

    int r0 = lane >> 2;
    int c2 = (lane & 3) * 2;
    int b_nrow = ((lane >> 4) & 1) * 8 + (lane & 7);
    int b_k    = ((lane >> 3) & 1) * 8;
    int v_row  = ((lane >> 3) & 1) * 8 + (lane & 7);
    int v_col  = (lane >> 4) * 8;

    const float* ksp = Kg + (size_t)row4 * DKH + c04;
    const float* vsp = Vg + (size_t)row4 * DKH + c04;

    for (int it = 0; it < S_LEN/64; it++) {
        int cur = it & 1;
        uint32_t sb = base + (uint32_t)cur * A_STAGE_B;
        bool more = it + 1 < S_LEN/64;

        // ---- prefetch next kv tile into registers ----
        float4 pk0, pk1, pk2, pk3, pv0, pv1, pv2, pv3;
        if (more) {
            const float* ks = ksp + (size_t)(it+1) * 64 * DKH;
            const float* vs = vsp + (size_t)(it+1) * 64 * DKH;
            pk0 = *(const float4*)(ks + 0);  pk1 = *(const float4*)(ks + 4);
            pk2 = *(const float4*)(ks + 8);  pk3 = *(const float4*)(ks + 12);
            pv0 = *(const float4*)(vs + 0);  pv1 = *(const float4*)(vs + 4);
            pv2 = *(const float4*)(vs + 8);  pv3 = *(const float4*)(vs + 12);
        }

        // ---- mask loads issued early (hidden behind QK MMAs) ----
        int k0 = it * 64;
        const int* mrow0 = mask + ((size_t)b * S_LEN + q0 + warp*16 + r0) * S_LEN + k0 + c2;
        const int* mrow1 = mrow0 + 8 * S_LEN;
        int2 mreg0[8], mreg1[8];
        #pragma unroll
        for (int nt = 0; nt < 8; nt++) {
            mreg0[nt] = *(const int2*)(mrow0 + nt*8);
            mreg1[nt] = *(const int2*)(mrow1 + nt*8);
        }

        // ---- S = Q K^T (single-term fp16) ----
        float S[8][4] = {};
        #pragma unroll
        for (int kt = 0; kt < 4; kt++) {
            uint32_t Bh[8][2];
            #pragma unroll
            for (int np = 0; np < 4; np++) {
                uint32_t x0, x1, x2, x3;
                uint32_t off = sb + (uint32_t)((np*16 + b_nrow)*LDK + kt*16 + b_k) * 2;
                ldsm_x4(x0, x1, x2, x3, off);
                Bh[np*2+0][0] = x0; Bh[np*2+0][1] = x1;
                Bh[np*2+1][0] = x2; Bh[np*2+1][1] = x3;
            }
            #pragma unroll
            for (int nt = 0; nt < 8; nt++)
                mma_f16(S[nt], Qh[kt], Bh[nt]);
        }

        // ---- mask + scale (log2 domain) ----
        #pragma unroll
        for (int nt = 0; nt < 8; nt++) {
            S[nt][0] = mreg0[nt].x ? S[nt][0] * MSCALE : MNEG;
            S[nt][1] = mreg0[nt].y ? S[nt][1] * MSCALE : MNEG;
            S[nt][2] = mreg1[nt].x ? S[nt][2] * MSCALE : MNEG;
            S[nt][3] = mreg1[nt].y ? S[nt][3] * MSCALE : MNEG;
        }

        // ---- online softmax (base-2) ----
        #pragma unroll
        for (int h = 0; h < 2; h++) {
            float mx = -1e30f;
            #pragma unroll
            for (int nt = 0; nt < 8; nt++)
                mx = fmaxf(mx, fmaxf(S[nt][2*h], S[nt][2*h+1]));
            mx = fmaxf(mx, __shfl_xor_sync(0xffffffffu, mx, 1));
            mx = fmaxf(mx, __shfl_xor_sync(0xffffffffu, mx, 2));
            float mnew  = fmaxf(m_i[h], mx);
            float alpha = exp2f(m_i[h] - mnew);
            m_i[h] = mnew;
            float ls = 0.f;
            #pragma unroll
            for (int nt = 0; nt < 8; nt++) {
                S[nt][2*h]   = exp2f(S[nt][2*h]   - mnew);
                S[nt][2*h+1] = exp2f(S[nt][2*h+1] - mnew);
                ls += S[nt][2*h] + S[nt][2*h+1];
            }
            ls += __shfl_xor_sync(0xffffffffu, ls, 1);
            ls += __shfl_xor_sync(0xffffffffu, ls, 2);
            l_i[h] = l_i[h] * alpha + ls;
            #pragma unroll
            for (int nt = 0; nt < 8; nt++) { O[nt][2*h] *= alpha; O[nt][2*h+1] *= alpha; }
        }

        // ---- O += P V (P single fp16, V hi/lo) ----
        #pragma unroll
        for (int kt = 0; kt < 4; kt++) {
            uint32_t Ah[4];
            Ah[0] = pack_h(S[2*kt+0][0], S[2*kt+0][1]);
            Ah[1] = pack_h(S[2*kt+0][2], S[2*kt+0][3]);
            Ah[2] = pack_h(S[2*kt+1][0], S[2*kt+1][1]);
            Ah[3] = pack_h(S[2*kt+1][2], S[2*kt+1][3]);

            uint32_t Vh[8][2], Vl[8][2];
            #pragma unroll
            for (int np = 0; np < 4; np++) {
                uint32_t x0, x1, x2, x3;
                uint32_t off = sb + 64*LDK*2 + (uint32_t)((kt*16 + v_row)*LDK + np*16 + v_col) * 2;
                ldsm_x4_t(x0, x1, x2, x3, off);
                Vh[np*2+0][0] = x0; Vh[np*2+0][1] = x1;
                Vh[np*2+1][0] = x2; Vh[np*2+1][1] = x3;
                ldsm_x4_t(x0, x1, x2, x3, off + 64*LDK*2);
                Vl[np*2+0][0] = x0; Vl[np*2+0][1] = x1;
                Vl[np*2+1][0] = x2; Vl[np*2+1][1] = x3;
            }
            #pragma unroll
            for (int nt = 0; nt < 8; nt++) {
                mma_f16(O[nt], Ah, Vh[nt]);
                mma_f16(O[nt], Ah, Vl[nt]);
            }
        }

        // ---- store prefetched tile into the other stage ----
        if (more) {
            __half* nx = dsm + (cur ^ 1) * A_STAGE_EL;
            cvt_store_h(pk0, pk1, nx + row4*LDK + c04);
            cvt_store_h(pk2, pk3, nx + row4*LDK + c04 + 8);
            split_store_h(pv0, pv1, nx + (64+row4)*LDK + c04,     nx + (128+row4)*LDK + c04);
            split_store_h(pv2, pv3, nx + (64+row4)*LDK + c04 + 8, nx + (128+row4)*LDK + c04 + 8);
        }
        __syncthreads();
    }

    // ---- finalize ----
    float inv0 = 1.0f / l_i[0];
    float inv1 = 1.0f / l_i[1];
    float* orow0 = g_attn + ((size_t)bh * S_LEN + q0 + warp*16 + r0) * DKH + c2;
    float* orow1 = orow0 + 8 * DKH;
    #pragma unroll
    for (int nt = 0; nt < 8; nt++) {
        *(float2*)(orow0 + nt*8) = make_float2(O[nt][0] * inv0, O[nt][1] * inv0);
        *(float2*)(orow1 + nt*8) = make_float2(O[nt][2] * inv1, O[nt][3] * inv1);
    }
}

extern "C" void kernel_launch(void* const* d_in, const int* in_sizes, int n_in,
                              void* d_out, int out_size)
{
    const float* query = (const float*)d_in[0];
    const float* key_  = (const float*)d_in[1];
    const float* value = (const float*)d_in[2];
    const int*   mask  = (const int*)d_in[3];
    const float* Wq = (const float*)d_in[4];
    const float* bq = (const float*)d_in[5];
    const float* Wk = (const float*)d_in[6];
    const float* bk = (const float*)d_in[7];
    const float* Wv = (const float*)d_in[8];
    const float* bv = (const float*)d_in[9];
    const float* Wo = (const float*)d_in[10];
    const float* bo = (const float*)d_in[11];
    float* out = (float*)d_out;

    cudaFuncSetAttribute(attn_kernel, cudaFuncAttributeMaxDynamicSharedMemorySize,
                         2 * A_STAGE_B);

    dim3 g1(DM / 128, (BB * S_LEN) / 128, 3);
    qkv_proj_kernel<<<g1, 256>>>(query, key_, value, Wq, bq, Wk, bk, Wv, bv);

    dim3 g2(S_LEN / 128, BB * NH);
    attn_kernel<<<g2, 256, 2 * A_STAGE_B>>>(mask);

    dim3 g3(DM / 128, (BB * S_LEN) / 128);
    out_proj_kernel<<<g3, 256>>>(Wo, bo, out);
}

// round 17
// speedup vs baseline: 1.0012x; 1.0012x over previous
#include <cuda_runtime.h>
#include <cuda_fp16.h>
#include <cstdint>

#define S_LEN 2048
#define DM    1024
#define NH    16
#define DKH   64
#define BB    2

// scratch: [B,H,S,DK] layouts
__device__ float g_q[BB*NH*S_LEN*DKH];
__device__ float g_k[BB*NH*S_LEN*DKH];
__device__ float g_v[BB*NH*S_LEN*DKH];
__device__ float g_attn[BB*NH*S_LEN*DKH];

// ---------------------------------------------------------------------------
// MMA helpers (warp-level, fp16 in / f32 out)
// ---------------------------------------------------------------------------
__device__ __forceinline__ void ldsm_x4(uint32_t& r0, uint32_t& r1, uint32_t& r2, uint32_t& r3,
                                        uint32_t addr) {
    asm volatile("ldmatrix.sync.aligned.m8n8.x4.shared.b16 {%0,%1,%2,%3}, [%4];"
                 : "=r"(r0), "=r"(r1), "=r"(r2), "=r"(r3) : "r"(addr));
}

__device__ __forceinline__ void ldsm_x4_t(uint32_t& r0, uint32_t& r1, uint32_t& r2, uint32_t& r3,
                                          uint32_t addr) {
    asm volatile("ldmatrix.sync.aligned.m8n8.x4.trans.shared.b16 {%0,%1,%2,%3}, [%4];"
                 : "=r"(r0), "=r"(r1), "=r"(r2), "=r"(r3) : "r"(addr));
}

__device__ __forceinline__ void mma_f16(float* c, const uint32_t* a, const uint32_t* b) {
    asm volatile(
        "mma.sync.aligned.m16n8k16.row.col.f32.f16.f16.f32 "
        "{%0,%1,%2,%3}, {%4,%5,%6,%7}, {%8,%9}, {%0,%1,%2,%3};"
        : "+f"(c[0]), "+f"(c[1]), "+f"(c[2]), "+f"(c[3])
        : "r"(a[0]), "r"(a[1]), "r"(a[2]), "r"(a[3]), "r"(b[0]), "r"(b[1]));
}

// split 8 floats into fp16 hi/lo and store 16B each
__device__ __forceinline__ void split_store_h(float4 u0, float4 u1,
                                              __half* dst_hi, __half* dst_lo) {
    float x[8] = {u0.x, u0.y, u0.z, u0.w, u1.x, u1.y, u1.z, u1.w};
    __half2 h[4], l[4];
    #pragma unroll
    for (int i = 0; i < 4; i++) {
        float a = x[2*i], b = x[2*i+1];
        __half ha = __float2half_rn(a);
        __half hb = __float2half_rn(b);
        __half la = __float2half_rn(a - __half2float(ha));
        __half lb = __float2half_rn(b - __half2float(hb));
        h[i] = __halves2half2(ha, hb);
        l[i] = __halves2half2(la, lb);
    }
    *(uint4*)dst_hi = *(uint4*)h;
    *(uint4*)dst_lo = *(uint4*)l;
}

// convert 8 floats to single fp16, store 16B
__device__ __forceinline__ void cvt_store_h(float4 u0, float4 u1, __half* dst) {
    __half2 h[4];
    h[0] = __floats2half2_rn(u0.x, u0.y);
    h[1] = __floats2half2_rn(u0.z, u0.w);
    h[2] = __floats2half2_rn(u1.x, u1.y);
    h[3] = __floats2half2_rn(u1.z, u1.w);
    *(uint4*)dst = *(uint4*)h;
}

__device__ __forceinline__ uint32_t pack_h(float a, float b) {
    __half2 t = __floats2half2_rn(a, b);
    return *(uint32_t*)&t;
}

// smem layout constants for the GEMM kernels (2-term: A single, B hi/lo)
#define LDAB 24                 // fp16 per row (16 data + 8 pad)
#define T_A    0
#define T_B_HI (128*LDAB)
#define T_B_LO (2*128*LDAB)
#define G_STAGE_EL (3*128*LDAB)     // elements per stage = 9216
#define G_STAGE_B  (G_STAGE_EL*2)   // bytes per stage = 18432

// ---------------------------------------------------------------------------
// QKV projection: double-buffered 2-term fp16 GEMM (A single, B split hi/lo).
// ---------------------------------------------------------------------------
__global__ __launch_bounds__(256, 2) void qkv_proj_kernel(
    const float* __restrict__ xq, const float* __restrict__ xk, const float* __restrict__ xv,
    const float* __restrict__ Wq, const float* __restrict__ bq,
    const float* __restrict__ Wk, const float* __restrict__ bk,
    const float* __restrict__ Wv, const float* __restrict__ bv)
{
    int z = blockIdx.z;
    const float* X    = (z == 0) ? xq : (z == 1) ? xk : xv;
    const float* W    = (z == 0) ? Wq : (z == 1) ? Wk : Wv;
    const float* bias = (z == 0) ? bq : (z == 1) ? bk : bv;
    float* out        = (z == 0) ? g_q : (z == 1) ? g_k : g_v;

    __shared__ __align__(16) __half sm[2*G_STAGE_EL];   // 36 KB

    int tid  = threadIdx.x;
    int lane = tid & 31;
    int wid  = tid >> 5;
    int wm   = wid & 1;
    int wn   = wid >> 1;
    int m0 = blockIdx.y * 128;
    int n0 = blockIdx.x * 128;

    int grow = tid >> 1;
    int gk8  = (tid & 1) * 8;
    const float* Abase = X + (size_t)(m0 + grow) * DM + gk8;
    const float* Bbase = W + (size_t)(n0 + grow) * DM + gk8;
    __half* sa    = sm + T_A    + grow * LDAB + gk8;
    __half* sb_hi = sm + T_B_HI + grow * LDAB + gk8;
    __half* sb_lo = sm + T_B_LO + grow * LDAB + gk8;

    uint32_t smem_u32 = (uint32_t)__cvta_generic_to_shared(sm);
    int a_row = lane & 15, a_kh = (lane >> 4) * 8;
    uint32_t adA[4];
    #pragma unroll
    for (int mt = 0; mt < 4; mt++) {
        int r = wm * 64 + mt * 16 + a_row;
        adA[mt] = smem_u32 + (uint32_t)(T_A + r * LDAB + a_kh) * 2;
    }
    int b_nrow = ((lane >> 4) & 1) * 8 + (lane & 7);
    int b_k    = ((lane >> 3) & 1) * 8;
    uint32_t adB[2], adBlo[2];
    #pragma unroll
    for (int p = 0; p < 2; p++) {
        int r = wn * 32 + p * 16 + b_nrow;
        adB[p]   = smem_u32 + (uint32_t)(T_B_HI + r * LDAB + b_k) * 2;
        adBlo[p] = smem_u32 + (uint32_t)(T_B_LO + r * LDAB + b_k) * 2;
    }

    float C[4][4][4] = {};

    float4 a0 = *(const float4*)(Abase + 0);
    float4 a1 = *(const float4*)(Abase + 4);
    float4 b0 = *(const float4*)(Bbase + 0);
    float4 b1 = *(const float4*)(Bbase + 4);

    cvt_store_h(a0, a1, sa);
    split_store_h(b0, b1, sb_hi, sb_lo);
    __syncthreads();

    uint32_t curB = 0;
    int      curE = 0;

    for (int k0 = 0; k0 < DM; k0 += 16) {
        bool more = (k0 + 16) < DM;
        if (more) {
            a0 = *(const float4*)(Abase + k0 + 16);
            a1 = *(const float4*)(Abase + k0 + 20);
            b0 = *(const float4*)(Bbase + k0 + 16);
            b1 = *(const float4*)(Bbase + k0 + 20);
        }

        uint32_t A[4][4], Bh[4][2], Bl[4][2];
        #pragma unroll
        for (int mt = 0; mt < 4; mt++)
            ldsm_x4(A[mt][0], A[mt][1], A[mt][2], A[mt][3], adA[mt] + curB);
        #pragma unroll
        for (int p = 0; p < 2; p++) {
            uint32_t r0, r1, r2, r3;
            ldsm_x4(r0, r1, r2, r3, adB[p] + curB);
            Bh[p*2+0][0] = r0; Bh[p*2+0][1] = r1;
            Bh[p*2+1][0] = r2; Bh[p*2+1][1] = r3;
            ldsm_x4(r0, r1, r2, r3, adBlo[p] + curB);
            Bl[p*2+0][0] = r0; Bl[p*2+0][1] = r1;
            Bl[p*2+1][0] = r2; Bl[p*2+1][1] = r3;
        }
        #pragma unroll
        for (int mt = 0; mt < 4; mt++)
            #pragma unroll
            for (int nt = 0; nt < 4; nt++) {
                mma_f16(C[mt][nt], A[mt], Bh[nt]);
                mma_f16(C[mt][nt], A[mt], Bl[nt]);
            }

        if (more) {
            int nx = curE ^ G_STAGE_EL;
            cvt_store_h(a0, a1, sa + nx);
            split_store_h(b0, b1, sb_hi + nx, sb_lo + nx);
        }
        __syncthreads();
        curB ^= G_STAGE_B;
        curE ^= G_STAGE_EL;
    }

    int crow = lane >> 2;
    int ccol = (lane & 3) * 2;
    #pragma unroll
    for (int nt = 0; nt < 4; nt++) {
        int n = n0 + wn * 32 + nt * 8 + ccol;
        int h = n >> 6, dk = n & 63;
        float bi0 = bias[n], bi1 = bias[n + 1];
        #pragma unroll
        for (int mt = 0; mt < 4; mt++) {
            #pragma unroll
            for (int half = 0; half < 2; half++) {
                int m = m0 + wm * 64 + mt * 16 + crow + half * 8;
                int b_ = m >> 11, s = m & 2047;
                float* op = out + (((size_t)(b_ * NH + h)) * S_LEN + s) * DKH + dk;
                float2 r = make_float2(C[mt][nt][half*2+0] + bi0, C[mt][nt][half*2+1] + bi1);
                *(float2*)op = r;
            }
        }
    }
}

// ---------------------------------------------------------------------------
// Output projection: same 2-term structure, head-gathered A.
// ---------------------------------------------------------------------------
__global__ __launch_bounds__(256, 2) void out_proj_kernel(
    const float* __restrict__ Wo, const float* __restrict__ bo, float* __restrict__ out)
{
    __shared__ __align__(16) __half sm[2*G_STAGE_EL];

    int tid  = threadIdx.x;
    int lane = tid & 31;
    int wid  = tid >> 5;
    int wm   = wid & 1;
    int wn   = wid >> 1;
    int m0 = blockIdx.y * 128;
    int n0 = blockIdx.x * 128;

    int grow = tid >> 1;
    int gk8  = (tid & 1) * 8;
    int m  = m0 + grow;
    int b_ = m >> 11, ss = m & 2047;
    const float* arow = g_attn + ((size_t)b_ * NH) * S_LEN * DKH + (size_t)ss * DKH;
    const float* Bbase = Wo + (size_t)(n0 + grow) * DM + gk8;
    __half* sa    = sm + T_A    + grow * LDAB + gk8;
    __half* sb_hi = sm + T_B_HI + grow * LDAB + gk8;
    __half* sb_lo = sm + T_B_LO + grow * LDAB + gk8;

    auto lda = [&](int k) -> float4 {
        return *(const float4*)(arow + (size_t)(k >> 6) * (S_LEN * DKH) + (k & 63));
    };

    uint32_t smem_u32 = (uint32_t)__cvta_generic_to_shared(sm);
    int a_row = lane & 15, a_kh = (lane >> 4) * 8;
    uint32_t adA[4];
    #pragma unroll
    for (int mt = 0; mt < 4; mt++) {
        int r = wm * 64 + mt * 16 + a_row;
        adA[mt] = smem_u32 + (uint32_t)(T_A + r * LDAB + a_kh) * 2;
    }
    int b_nrow = ((lane >> 4) & 1) * 8 + (lane & 7);
    int b_k    = ((lane >> 3) & 1) * 8;
    uint32_t adB[2], adBlo[2];
    #pragma unroll
    for (int p = 0; p < 2; p++) {
        int r = wn * 32 + p * 16 + b_nrow;
        adB[p]   = smem_u32 + (uint32_t)(T_B_HI + r * LDAB + b_k) * 2;
        adBlo[p] = smem_u32 + (uint32_t)(T_B_LO + r * LDAB + b_k) * 2;
    }

    float C[4][4][4] = {};

    float4 a0 = lda(gk8);
    float4 a1 = lda(gk8 + 4);
    float4 b0 = *(const float4*)(Bbase + 0);
    float4 b1 = *(const float4*)(Bbase + 4);

    cvt_store_h(a0, a1, sa);
    split_store_h(b0, b1, sb_hi, sb_lo);
    __syncthreads();

    uint32_t curB = 0;
    int      curE = 0;

    for (int k0 = 0; k0 < DM; k0 += 16) {
        bool more = (k0 + 16) < DM;
        if (more) {
            a0 = lda(k0 + 16 + gk8);
            a1 = lda(k0 + 16 + gk8 + 4);
            b0 = *(const float4*)(Bbase + k0 + 16);
            b1 = *(const float4*)(Bbase + k0 + 20);
        }

        uint32_t A[4][4], Bh[4][2], Bl[4][2];
        #pragma unroll
        for (int mt = 0; mt < 4; mt++)
            ldsm_x4(A[mt][0], A[mt][1], A[mt][2], A[mt][3], adA[mt] + curB);
        #pragma unroll
        for (int p = 0; p < 2; p++) {
            uint32_t r0, r1, r2, r3;
            ldsm_x4(r0, r1, r2, r3, adB[p] + curB);
            Bh[p*2+0][0] = r0; Bh[p*2+0][1] = r1;
            Bh[p*2+1][0] = r2; Bh[p*2+1][1] = r3;
            ldsm_x4(r0, r1, r2, r3, adBlo[p] + curB);
            Bl[p*2+0][0] = r0; Bl[p*2+0][1] = r1;
            Bl[p*2+1][0] = r2; Bl[p*2+1][1] = r3;
        }
        #pragma unroll
        for (int mt = 0; mt < 4; mt++)
            #pragma unroll
            for (int nt = 0; nt < 4; nt++) {
                mma_f16(C[mt][nt], A[mt], Bh[nt]);
                mma_f16(C[mt][nt], A[mt], Bl[nt]);
            }

        if (more) {
            int nx = curE ^ G_STAGE_EL;
            cvt_store_h(a0, a1, sa + nx);
            split_store_h(b0, b1, sb_hi + nx, sb_lo + nx);
        }
        __syncthreads();
        curB ^= G_STAGE_B;
        curE ^= G_STAGE_EL;
    }

    int crow = lane >> 2;
    int ccol = (lane & 3) * 2;
    #pragma unroll
    for (int nt = 0; nt < 4; nt++) {
        int n = n0 + wn * 32 + nt * 8 + ccol;
        float bi0 = bo[n], bi1 = bo[n + 1];
        #pragma unroll
        for (int mt = 0; mt < 4; mt++) {
            #pragma unroll
            for (int half = 0; half < 2; half++) {
                int mr = m0 + wm * 64 + mt * 16 + crow + half * 8;
                float2 r = make_float2(C[mt][nt][half*2+0] + bi0, C[mt][nt][half*2+1] + bi1);
                *(float2*)(out + (size_t)mr * DM + n) = r;
            }
        }
    }
}

// ---------------------------------------------------------------------------
// Flash attention (unchanged from R9): QK = Qh*Kh [1 MMA], PV = P*(Vh+Vl) [2 MMA].
// CTA: 128 q rows x one (b,h); 8 warps x 16 q rows; kv tiles of 64, 2-stage.
// Stage layout (rows of LDK): K single [0-63], V hi [64-127], V lo [128-191].
// ---------------------------------------------------------------------------
#define LDK 72
#define A_STAGE_EL (192*LDK)        // elements per stage = 13824
#define A_STAGE_B  (A_STAGE_EL*2)   // 27648 bytes

extern __shared__ __half dsm[];

__global__ __launch_bounds__(256) void attn_kernel(const int* __restrict__ mask)
{
    const float MSCALE = 0.125f * 1.44269504f;   // (1/8) * log2(e)
    const float MNEG   = -1.442695e9f;           // -1e9 * log2(e)

    int tid  = threadIdx.x;
    int lane = tid & 31;
    int warp = tid >> 5;
    int bh = blockIdx.y;
    int b  = bh >> 4;
    int q0 = blockIdx.x * 128;

    const float* Qg = g_q + (size_t)bh * S_LEN * DKH;
    const float* Kg = g_k + (size_t)bh * S_LEN * DKH;
    const float* Vg = g_v + (size_t)bh * S_LEN * DKH;

    uint32_t base = (uint32_t)__cvta_generic_to_shared(dsm);

    // ---- stage Q (single fp16) into stage0 rows 0-127 ----
    {
        int row = tid >> 1;
        int c0 = (tid & 1) * 32;
        const float* src = Qg + (size_t)(q0 + row) * DKH + c0;
        #pragma unroll
        for (int c = 0; c < 32; c += 8) {
            float4 u0 = *(const float4*)(src + c);
            float4 u1 = *(const float4*)(src + c + 4);
            cvt_store_h(u0, u1, dsm + row*LDK + c0 + c);
        }
    }
    __syncthreads();

    // ---- Q A-fragments (resident all kernel) ----
    uint32_t Qh[4][4];
    {
        int a_row = lane & 15, a_kh = (lane >> 4) * 8;
        #pragma unroll
        for (int kt = 0; kt < 4; kt++) {
            uint32_t off = (uint32_t)((warp*16 + a_row)*LDK + kt*16 + a_kh) * 2;
            ldsm_x4(Qh[kt][0], Qh[kt][1], Qh[kt][2], Qh[kt][3], base + off);
        }
    }
    __syncthreads();   // done reading Q staging before overwriting stage0

    // ---- stage kv tile 0 into stage0 ----
    int row4 = tid >> 2;           // 0..63
    int c04  = (tid & 3) * 16;     // 0,16,32,48
    {
        const float* ks = Kg + (size_t)row4 * DKH + c04;
        const float* vs = Vg + (size_t)row4 * DKH + c04;
        float4 k0_ = *(const float4*)(ks + 0), k1_ = *(const float4*)(ks + 4);
        float4 k2_ = *(const float4*)(ks + 8), k3_ = *(const float4*)(ks + 12);
        cvt_store_h(k0_, k1_, dsm + row4*LDK + c04);
        cvt_store_h(k2_, k3_, dsm + row4*LDK + c04 + 8);
        float4 w0 = *(const float4*)(vs + 0), w1 = *(const float4*)(vs + 4);
        float4 w2 = *(const float4*)(vs + 8), w3 = *(const float4*)(vs + 12);
        split_store_h(w0, w1, dsm + (64+row4)*LDK + c04,     dsm + (128+row4)*LDK + c04);
        split_store_h(w2, w3, dsm + (64+row4)*LDK + c04 + 8, dsm + (128+row4)*LDK + c04 + 8);
    }
    __syncthreads();

    float m_i[2] = {-1e30f, -1e30f};
    float l_i[2] = {0.f, 0.f};
    float O[8][4] = {};

    int r0 = lane >> 2;
    int c2 = (lane & 3) * 2;
    int b_nrow = ((lane >> 4) & 1) * 8 + (lane & 7);
    int b_k    = ((lane >> 3) & 1) * 8;
    int v_row  = ((lane >> 3) & 1) * 8 + (lane & 7);
    int v_col  = (lane >> 4) * 8;

    const float* ksp = Kg + (size_t)row4 * DKH + c04;
    const float* vsp = Vg + (size_t)row4 * DKH + c04;

    for (int it = 0; it < S_LEN/64; it++) {
        int cur = it & 1;
        uint32_t sb = base + (uint32_t)cur * A_STAGE_B;
        bool more = it + 1 < S_LEN/64;

        // ---- prefetch next kv tile into registers ----
        float4 pk0, pk1, pk2, pk3, pv0, pv1, pv2, pv3;
        if (more) {
            const float* ks = ksp + (size_t)(it+1) * 64 * DKH;
            const float* vs = vsp + (size_t)(it+1) * 64 * DKH;
            pk0 = *(const float4*)(ks + 0);  pk1 = *(const float4*)(ks + 4);
            pk2 = *(const float4*)(ks + 8);  pk3 = *(const float4*)(ks + 12);
            pv0 = *(const float4*)(vs + 0);  pv1 = *(const float4*)(vs + 4);
            pv2 = *(const float4*)(vs + 8);  pv3 = *(const float4*)(vs + 12);
        }

        // ---- mask loads issued early (hidden behind QK MMAs) ----
        int k0 = it * 64;
        const int* mrow0 = mask + ((size_t)b * S_LEN + q0 + warp*16 + r0) * S_LEN + k0 + c2;
        const int* mrow1 = mrow0 + 8 * S_LEN;
        int2 mreg0[8], mreg1[8];
        #pragma unroll
        for (int nt = 0; nt < 8; nt++) {
            mreg0[nt] = *(const int2*)(mrow0 + nt*8);
            mreg1[nt] = *(const int2*)(mrow1 + nt*8);
        }

        // ---- S = Q K^T (single-term fp16) ----
        float S[8][4] = {};
        #pragma unroll
        for (int kt = 0; kt < 4; kt++) {
            uint32_t Bh[8][2];
            #pragma unroll
            for (int np = 0; np < 4; np++) {
                uint32_t x0, x1, x2, x3;
                uint32_t off = sb + (uint32_t)((np*16 + b_nrow)*LDK + kt*16 + b_k) * 2;
                ldsm_x4(x0, x1, x2, x3, off);
                Bh[np*2+0][0] = x0; Bh[np*2+0][1] = x1;
                Bh[np*2+1][0] = x2; Bh[np*2+1][1] = x3;
            }
            #pragma unroll
            for (int nt = 0; nt < 8; nt++)
                mma_f16(S[nt], Qh[kt], Bh[nt]);
        }

        // ---- mask + scale (log2 domain) ----
        #pragma unroll
        for (int nt = 0; nt < 8; nt++) {
            S[nt][0] = mreg0[nt].x ? S[nt][0] * MSCALE : MNEG;
            S[nt][1] = mreg0[nt].y ? S[nt][1] * MSCALE : MNEG;
            S[nt][2] = mreg1[nt].x ? S[nt][2] * MSCALE : MNEG;
            S[nt][3] = mreg1[nt].y ? S[nt][3] * MSCALE : MNEG;
        }

        // ---- online softmax (base-2) ----
        #pragma unroll
        for (int h = 0; h < 2; h++) {
            float mx = -1e30f;
            #pragma unroll
            for (int nt = 0; nt < 8; nt++)
                mx = fmaxf(mx, fmaxf(S[nt][2*h], S[nt][2*h+1]));
            mx = fmaxf(mx, __shfl_xor_sync(0xffffffffu, mx, 1));
            mx = fmaxf(mx, __shfl_xor_sync(0xffffffffu, mx, 2));
            float mnew  = fmaxf(m_i[h], mx);
            float alpha = exp2f(m_i[h] - mnew);
            m_i[h] = mnew;
            float ls = 0.f;
            #pragma unroll
            for (int nt = 0; nt < 8; nt++) {
                S[nt][2*h]   = exp2f(S[nt][2*h]   - mnew);
                S[nt][2*h+1] = exp2f(S[nt][2*h+1] - mnew);
                ls += S[nt][2*h] + S[nt][2*h+1];
            }
            ls += __shfl_xor_sync(0xffffffffu, ls, 1);
            ls += __shfl_xor_sync(0xffffffffu, ls, 2);
            l_i[h] = l_i[h] * alpha + ls;
            #pragma unroll
            for (int nt = 0; nt < 8; nt++) { O[nt][2*h] *= alpha; O[nt][2*h+1] *= alpha; }
        }

        // ---- O += P V (P single fp16, V hi/lo) ----
        #pragma unroll
        for (int kt = 0; kt < 4; kt++) {
            uint32_t Ah[4];
            Ah[0] = pack_h(S[2*kt+0][0], S[2*kt+0][1]);
            Ah[1] = pack_h(S[2*kt+0][2], S[2*kt+0][3]);
            Ah[2] = pack_h(S[2*kt+1][0], S[2*kt+1][1]);
            Ah[3] = pack_h(S[2*kt+1][2], S[2*kt+1][3]);

            uint32_t Vh[8][2], Vl[8][2];
            #pragma unroll
            for (int np = 0; np < 4; np++) {
                uint32_t x0, x1, x2, x3;
                uint32_t off = sb + 64*LDK*2 + (uint32_t)((kt*16 + v_row)*LDK + np*16 + v_col) * 2;
                ldsm_x4_t(x0, x1, x2, x3, off);
                Vh[np*2+0][0] = x0; Vh[np*2+0][1] = x1;
                Vh[np*2+1][0] = x2; Vh[np*2+1][1] = x3;
                ldsm_x4_t(x0, x1, x2, x3, off + 64*LDK*2);
                Vl[np*2+0][0] = x0; Vl[np*2+0][1] = x1;
                Vl[np*2+1][0] = x2; Vl[np*2+1][1] = x3;
            }
            #pragma unroll
            for (int nt = 0; nt < 8; nt++) {
                mma_f16(O[nt], Ah, Vh[nt]);
                mma_f16(O[nt], Ah, Vl[nt]);
            }
        }

        // ---- store prefetched tile into the other stage ----
        if (more) {
            __half* nx = dsm + (cur ^ 1) * A_STAGE_EL;
            cvt_store_h(pk0, pk1, nx + row4*LDK + c04);
            cvt_store_h(pk2, pk3, nx + row4*LDK + c04 + 8);
            split_store_h(pv0, pv1, nx + (64+row4)*LDK + c04,     nx + (128+row4)*LDK + c04);
            split_store_h(pv2, pv3, nx + (64+row4)*LDK + c04 + 8, nx + (128+row4)*LDK + c04 + 8);
        }
        __syncthreads();
    }

    // ---- finalize ----
    float inv0 = 1.0f / l_i[0];
    float inv1 = 1.0f / l_i[1];
    float* orow0 = g_attn + ((size_t)bh * S_LEN + q0 + warp*16 + r0) * DKH + c2;
    float* orow1 = orow0 + 8 * DKH;
    #pragma unroll
    for (int nt = 0; nt < 8; nt++) {
        *(float2*)(orow0 + nt*8) = make_float2(O[nt][0] * inv0, O[nt][1] * inv0);
        *(float2*)(orow1 + nt*8) = make_float2(O[nt][2] * inv1, O[nt][3] * inv1);
    }
}

extern "C" void kernel_launch(void* const* d_in, const int* in_sizes, int n_in,
                              void* d_out, int out_size)
{
    const float* query = (const float*)d_in[0];
    const float* key_  = (const float*)d_in[1];
    const float* value = (const float*)d_in[2];
    const int*   mask  = (const int*)d_in[3];
    const float* Wq = (const float*)d_in[4];
    const float* bq = (const float*)d_in[5];
    const float* Wk = (const float*)d_in[6];
    const float* bk = (const float*)d_in[7];
    const float* Wv = (const float*)d_in[8];
    const float* bv = (const float*)d_in[9];
    const float* Wo = (const float*)d_in[10];
    const float* bo = (const float*)d_in[11];
    float* out = (float*)d_out;

    cudaFuncSetAttribute(attn_kernel, cudaFuncAttributeMaxDynamicSharedMemorySize,
                         2 * A_STAGE_B);

    dim3 g1(DM / 128, (BB * S_LEN) / 128, 3);
    qkv_proj_kernel<<<g1, 256>>>(query, key_, value, Wq, bq, Wk, bk, Wv, bv);

    dim3 g2(S_LEN / 128, BB * NH);
    attn_kernel<<<g2, 256, 2 * A_STAGE_B>>>(mask);

    dim3 g3(DM / 128, (BB * S_LEN) / 128);
    out_proj_kernel<<<g3, 256>>>(Wo, bo, out);
}